// round 5
// baseline (speedup 1.0000x reference)
#include <cuda_runtime.h>
#include <cuda_fp16.h>

#define NN 6144
#define FF 128
#define CC 64
#define HH 4
#define MAXNB 384

typedef unsigned long long ull;

#define PACK2(out, lo, hi) \
    asm("mov.b64 %0, {%1, %2};" : "=l"(out) : "f"(lo), "f"(hi))
#define UNPACK2(lo, hi, in) \
    asm("mov.b64 {%0, %1}, %2;" : "=f"(lo), "=f"(hi) : "l"(in))
#define FMA2(d, a, b, c) \
    asm("fma.rn.f32x2 %0, %1, %2, %3;" : "=l"(d) : "l"(a), "l"(b), "l"(c))

// Scratch (allocation-free: __device__ globals)
__device__ __half g_featsh[HH * NN * CC];  // X@W1 per head (fp16, gather operand)
__device__ float  g_feats2[HH * NN * CC];  // X@W2 per head (fp32, base term)
__device__ float  g_atts  [HH * NN];       // self logit term (fp32)
__device__ float  g_attn  [HH * NN];       // neighbor logit term (fp32)

// ---------------------------------------------------------------------------
// k_proj: tiled SGEMM with f32x2 packed FFMA + att-vector epilogue.
// grid (48, 8): y = head*2 + {0:W1, 1:W2}. BM=128, BN=64(=C), BK=32,
// 256 threads. Thread tile 8 rows x 4 cols, rows packed in pairs (FFMA2).
// W1 blocks emit fp16 feats + fp32 att_s/att_n; W2 blocks emit fp32 feats2.
// ---------------------------------------------------------------------------
__global__ __launch_bounds__(256) void k_proj(
    const float* __restrict__ X,
    const float* __restrict__ W1,
    const float* __restrict__ W2,
    const float* __restrict__ a_self,
    const float* __restrict__ a_neigh)
{
    __shared__ float Xs[32][132];   // [k][m], stride 132 (16B-aligned rows)
    __shared__ float Ws[32][64];    // [k][n]

    const int tid  = threadIdx.x;
    const int n0   = blockIdx.x * 128;
    const int head = blockIdx.y >> 1;
    const int isw2 = blockIdx.y & 1;
    const float* Wsrc = (isw2 ? W2 : W1) + (size_t)head * FF * CC;

    const int tx = tid & 15;        // col group: c0 = tx*4
    const int ty = tid >> 4;        // row group: r0 = ty*8
    const int c0 = tx * 4;
    const int r0 = ty * 8;

    ull acc[4][4];                  // [rowpair][col], each = (row2rp, row2rp+1)
    #pragma unroll
    for (int rp = 0; rp < 4; ++rp)
        acc[rp][0] = acc[rp][1] = acc[rp][2] = acc[rp][3] = 0ull;

    for (int kt = 0; kt < 4; ++kt) {
        #pragma unroll
        for (int l = 0; l < 4; ++l) {
            int lin = tid + l * 256;
            int row = lin >> 3;
            int f4  = lin & 7;
            float4 v = *(const float4*)(X + (size_t)(n0 + row) * FF + kt * 32 + f4 * 4);
            Xs[f4 * 4 + 0][row] = v.x;
            Xs[f4 * 4 + 1][row] = v.y;
            Xs[f4 * 4 + 2][row] = v.z;
            Xs[f4 * 4 + 3][row] = v.w;
        }
        #pragma unroll
        for (int l = 0; l < 2; ++l) {
            int lin = tid + l * 256;
            int k  = lin >> 4;
            int c4 = lin & 15;
            *(float4*)&Ws[k][c4 * 4] =
                *(const float4*)(Wsrc + (size_t)(kt * 32 + k) * CC + c4 * 4);
        }
        __syncthreads();

        #pragma unroll 8
        for (int k = 0; k < 32; ++k) {
            ulonglong2 xa = *(const ulonglong2*)&Xs[k][r0];
            ulonglong2 xb = *(const ulonglong2*)&Xs[k][r0 + 4];
            float4 w = *(const float4*)&Ws[k][c0];
            ull wx, wy, wz, ww;
            PACK2(wx, w.x, w.x);
            PACK2(wy, w.y, w.y);
            PACK2(wz, w.z, w.z);
            PACK2(ww, w.w, w.w);
            FMA2(acc[0][0], xa.x, wx, acc[0][0]);
            FMA2(acc[0][1], xa.x, wy, acc[0][1]);
            FMA2(acc[0][2], xa.x, wz, acc[0][2]);
            FMA2(acc[0][3], xa.x, ww, acc[0][3]);
            FMA2(acc[1][0], xa.y, wx, acc[1][0]);
            FMA2(acc[1][1], xa.y, wy, acc[1][1]);
            FMA2(acc[1][2], xa.y, wz, acc[1][2]);
            FMA2(acc[1][3], xa.y, ww, acc[1][3]);
            FMA2(acc[2][0], xb.x, wx, acc[2][0]);
            FMA2(acc[2][1], xb.x, wy, acc[2][1]);
            FMA2(acc[2][2], xb.x, wz, acc[2][2]);
            FMA2(acc[2][3], xb.x, ww, acc[2][3]);
            FMA2(acc[3][0], xb.y, wx, acc[3][0]);
            FMA2(acc[3][1], xb.y, wy, acc[3][1]);
            FMA2(acc[3][2], xb.y, wz, acc[3][2]);
            FMA2(acc[3][3], xb.y, ww, acc[3][3]);
        }
        __syncthreads();
    }

    const float4 as = *(const float4*)(a_self  + head * CC + c0);
    const float4 an = *(const float4*)(a_neigh + head * CC + c0);

    #pragma unroll
    for (int rp = 0; rp < 4; ++rp) {
        float lo0, hi0, lo1, hi1, lo2, hi2, lo3, hi3;
        UNPACK2(lo0, hi0, acc[rp][0]);
        UNPACK2(lo1, hi1, acc[rp][1]);
        UNPACK2(lo2, hi2, acc[rp][2]);
        UNPACK2(lo3, hi3, acc[rp][3]);

        if (isw2) {
            float* dst = g_feats2 + ((size_t)head * NN + n0 + r0) * CC + c0;
            *(float4*)(dst + (size_t)(2 * rp) * CC)     = make_float4(lo0, lo1, lo2, lo3);
            *(float4*)(dst + (size_t)(2 * rp + 1) * CC) = make_float4(hi0, hi1, hi2, hi3);
        } else {
            // fp16 feats store (8 B per row segment)
            __half* dsth = g_featsh + ((size_t)head * NN + n0 + r0) * CC + c0;
            __half2 l01 = __floats2half2_rn(lo0, lo1);
            __half2 l23 = __floats2half2_rn(lo2, lo3);
            __half2 h01 = __floats2half2_rn(hi0, hi1);
            __half2 h23 = __floats2half2_rn(hi2, hi3);
            uint2 pl, ph;
            pl.x = *(unsigned*)&l01;  pl.y = *(unsigned*)&l23;
            ph.x = *(unsigned*)&h01;  ph.y = *(unsigned*)&h23;
            *(uint2*)(dsth + (size_t)(2 * rp) * CC)     = pl;
            *(uint2*)(dsth + (size_t)(2 * rp + 1) * CC) = ph;

            // att-vector epilogue (fp32, unchanged precision)
            float s0 = lo0 * as.x + lo1 * as.y + lo2 * as.z + lo3 * as.w;
            float t0 = lo0 * an.x + lo1 * an.y + lo2 * an.z + lo3 * an.w;
            float s1 = hi0 * as.x + hi1 * as.y + hi2 * as.z + hi3 * as.w;
            float t1 = hi0 * an.x + hi1 * an.y + hi2 * an.z + hi3 * an.w;
            #pragma unroll
            for (int o = 8; o; o >>= 1) {
                s0 += __shfl_xor_sync(0xffffffffu, s0, o);
                t0 += __shfl_xor_sync(0xffffffffu, t0, o);
                s1 += __shfl_xor_sync(0xffffffffu, s1, o);
                t1 += __shfl_xor_sync(0xffffffffu, t1, o);
            }
            if (tx == 0) {
                g_atts[head * NN + n0 + r0 + 2 * rp]     = s0;
                g_attn[head * NN + n0 + r0 + 2 * rp]     = t0;
                g_atts[head * NN + n0 + r0 + 2 * rp + 1] = s1;
                g_attn[head * NN + n0 + r0 + 2 * rp + 1] = t1;
            }
        }
    }
}

// ---------------------------------------------------------------------------
// k_attn: one 128-thread block per row; bitmask compaction (A read ONCE,
// coalesced); one warp per head; fp16 half2 gather (1 LDG per j per lane).
// ---------------------------------------------------------------------------
__global__ __launch_bounds__(128) void k_attn(
    const float* __restrict__ A,
    const float* __restrict__ bias,
    float* __restrict__ out)
{
    __shared__ int   s_idx[MAXNB + 4];
    __shared__ float s_e[HH][MAXNB + 4];
    __shared__ int   s_wsum[4];
    __shared__ float s_out[HH][CC];

    const int i    = blockIdx.x;
    const int tid  = threadIdx.x;
    const int lane = tid & 31;
    const int warp = tid >> 5;
    const float* Ai = A + (size_t)i * NN;

    // --- coalesced scan, presence bitmask in a register ---
    unsigned long long mask = 0ull;
    #pragma unroll
    for (int k = 0; k < 12; ++k) {
        float4 v = *(const float4*)(Ai + 4 * tid + 512 * k);
        unsigned m = (unsigned)(v.x != 0.f)
                   | ((unsigned)(v.y != 0.f) << 1)
                   | ((unsigned)(v.z != 0.f) << 2)
                   | ((unsigned)(v.w != 0.f) << 3);
        mask |= (unsigned long long)m << (4 * k);
    }
    const int lc = __popcll(mask);

    // --- warp shfl scan + cross-warp combine ---
    int v = lc;
    #pragma unroll
    for (int o = 1; o < 32; o <<= 1) {
        int u = __shfl_up_sync(0xffffffffu, v, o);
        if (lane >= o) v += u;
    }
    if (lane == 31) s_wsum[warp] = v;
    __syncthreads();
    int base = 0;
    #pragma unroll
    for (int w = 0; w < 4; ++w)
        if (w < warp) base += s_wsum[w];
    int cnt = s_wsum[0] + s_wsum[1] + s_wsum[2] + s_wsum[3];
    if (cnt > MAXNB) cnt = MAXNB;

    // --- compaction from the bitmask (no global re-read) ---
    int p = base + v - lc;
    unsigned long long m2 = mask;
    while (m2) {
        int b = __ffsll((long long)m2) - 1;
        m2 &= m2 - 1;
        int col = 4 * tid + 512 * (b >> 2) + (b & 3);
        if (p < MAXNB) s_idx[p] = col;
        ++p;
    }
    if (tid < 3) s_idx[cnt + tid] = 0;       // pad for int4 gather reads
    __syncthreads();

    // --- per-head processing: warp h owns head h ---
    const int h = warp;
    const float si = g_atts[h * NN + i];
    const float* an = g_attn + (size_t)h * NN;

    float lmax = -1e30f;
    for (int j = lane; j < cnt; j += 32) {
        float l = si + an[s_idx[j]];
        l = (l > 0.f) ? l : 0.2f * l;        // LeakyReLU(0.2)
        s_e[h][j] = l;
        lmax = fmaxf(lmax, l);
    }
    #pragma unroll
    for (int o = 16; o; o >>= 1)
        lmax = fmaxf(lmax, __shfl_xor_sync(0xffffffffu, lmax, o));
    __syncwarp();

    float lsum = 0.f;
    for (int j = lane; j < cnt; j += 32) {
        float e = __expf(s_e[h][j] - lmax);
        s_e[h][j] = e;
        lsum += e;
    }
    if (lane < 3) s_e[h][cnt + lane] = 0.f;  // pad for float4 gather reads
    #pragma unroll
    for (int o = 16; o; o >>= 1)
        lsum += __shfl_xor_sync(0xffffffffu, lsum, o);
    float inv = 1.f / lsum;
    __syncwarp();

    // gather-aggregate: lane owns channels (2*lane, 2*lane+1); one half2
    // load per neighbor per lane; 4 neighbors per iteration.
    const __half2* fh = (const __half2*)(g_featsh + (size_t)h * NN * CC);
    float acc0 = 0.f, acc1 = 0.f;
    for (int j = 0; j < cnt; j += 4) {
        float4 e4 = *(const float4*)&s_e[h][j];
        int4   i4 = *(const int4*)&s_idx[j];
        float2 f0 = __half22float2(fh[(size_t)i4.x * (CC / 2) + lane]);
        float2 f1 = __half22float2(fh[(size_t)i4.y * (CC / 2) + lane]);
        float2 f2 = __half22float2(fh[(size_t)i4.z * (CC / 2) + lane]);
        float2 f3 = __half22float2(fh[(size_t)i4.w * (CC / 2) + lane]);
        acc0 += e4.x * f0.x;   acc1 += e4.x * f0.y;
        acc0 += e4.y * f1.x;   acc1 += e4.y * f1.y;
        acc0 += e4.z * f2.x;   acc1 += e4.z * f2.y;
        acc0 += e4.w * f3.x;   acc1 += e4.w * f3.y;
    }
    s_out[h][2 * lane]     = acc0 * inv;
    s_out[h][2 * lane + 1] = acc1 * inv;
    __syncthreads();

    if (tid < CC) {
        float b = 0.f;
        #pragma unroll
        for (int hh = 0; hh < HH; ++hh)
            b += g_feats2[((size_t)hh * NN + i) * CC + tid] + bias[hh * CC + tid];
        float o = 0.25f * b
                + 0.25f * (s_out[0][tid] + s_out[1][tid] + s_out[2][tid] + s_out[3][tid]);
        out[(size_t)i * CC + tid] = (o > 0.f) ? o : 0.f;
    }
}

// ---------------------------------------------------------------------------
extern "C" void kernel_launch(void* const* d_in, const int* in_sizes, int n_in,
                              void* d_out, int out_size)
{
    const float* X       = (const float*)d_in[0];
    const float* A       = (const float*)d_in[1];
    const float* W1      = (const float*)d_in[2];
    const float* W2      = (const float*)d_in[3];
    const float* a_self  = (const float*)d_in[4];
    const float* a_neigh = (const float*)d_in[5];
    const float* bias    = (const float*)d_in[6];
    float* out = (float*)d_out;

    k_proj<<<dim3(48, 8), 256>>>(X, W1, W2, a_self, a_neigh);
    k_attn<<<NN,          128>>>(A, bias, out);
}

// round 6
// speedup vs baseline: 1.2473x; 1.2473x over previous
#include <cuda_runtime.h>

#define NN 6144
#define FF 128
#define CC 64
#define HH 4
#define MAXNB 384

typedef unsigned long long ull;

#define PACK2(out, lo, hi) \
    asm("mov.b64 %0, {%1, %2};" : "=l"(out) : "f"(lo), "f"(hi))
#define UNPACK2(lo, hi, in) \
    asm("mov.b64 {%0, %1}, %2;" : "=f"(lo), "=f"(hi) : "l"(in))
#define FMA2(d, a, b, c) \
    asm("fma.rn.f32x2 %0, %1, %2, %3;" : "=l"(d) : "l"(a), "l"(b), "l"(c))

// Scratch (allocation-free: __device__ globals)
__device__ float g_feats [HH * NN * CC];  // X@W1 per head (fp32)
__device__ float g_feats2[HH * NN * CC];  // X@W2 per head (fp32)
__device__ float g_atts  [HH * NN];       // self logit term
__device__ float g_attn  [HH * NN];       // neighbor logit term
__device__ ull   g_mask  [NN * 128];      // 48-bit presence words per row

// ---------------------------------------------------------------------------
// k_mask: pure-streaming adjacency scan. 2 rows per 256-thread CTA.
// Word t of row i covers cols {4t + 512k + e : k<12, e<4} (same layout the
// attn kernel's compaction decodes).
// ---------------------------------------------------------------------------
__global__ __launch_bounds__(256) void k_mask(const float* __restrict__ A)
{
    const int tid = threadIdx.x;
    const int t   = tid & 127;                 // word within row
    const int i   = blockIdx.x * 2 + (tid >> 7);
    const float* Ai = A + (size_t)i * NN;

    ull mask = 0ull;
    #pragma unroll
    for (int k = 0; k < 12; ++k) {
        float4 v = *(const float4*)(Ai + 4 * t + 512 * k);
        unsigned m = (unsigned)(v.x != 0.f)
                   | ((unsigned)(v.y != 0.f) << 1)
                   | ((unsigned)(v.z != 0.f) << 2)
                   | ((unsigned)(v.w != 0.f) << 3);
        mask |= (ull)m << (4 * k);
    }
    g_mask[(size_t)i * 128 + t] = mask;
}

// ---------------------------------------------------------------------------
// k_proj: tiled SGEMM with f32x2 packed FFMA + att-vector epilogue.
// grid (48, 8): y = head*2 + {0:W1, 1:W2}. BM=128, BN=64(=C), BK=32,
// 256 threads. Thread tile 8 rows x 4 cols, rows packed in pairs (FFMA2).
// ---------------------------------------------------------------------------
__global__ __launch_bounds__(256) void k_proj(
    const float* __restrict__ X,
    const float* __restrict__ W1,
    const float* __restrict__ W2,
    const float* __restrict__ a_self,
    const float* __restrict__ a_neigh)
{
    __shared__ float Xs[32][132];   // [k][m], stride 132 (16B-aligned rows)
    __shared__ float Ws[32][64];    // [k][n]

    const int tid  = threadIdx.x;
    const int n0   = blockIdx.x * 128;
    const int head = blockIdx.y >> 1;
    const int isw2 = blockIdx.y & 1;
    const float* Wsrc = (isw2 ? W2 : W1) + (size_t)head * FF * CC;

    const int tx = tid & 15;        // col group: c0 = tx*4
    const int ty = tid >> 4;        // row group: r0 = ty*8
    const int c0 = tx * 4;
    const int r0 = ty * 8;

    ull acc[4][4];                  // [rowpair][col]
    #pragma unroll
    for (int rp = 0; rp < 4; ++rp)
        acc[rp][0] = acc[rp][1] = acc[rp][2] = acc[rp][3] = 0ull;

    for (int kt = 0; kt < 4; ++kt) {
        #pragma unroll
        for (int l = 0; l < 4; ++l) {
            int lin = tid + l * 256;
            int row = lin >> 3;
            int f4  = lin & 7;
            float4 v = *(const float4*)(X + (size_t)(n0 + row) * FF + kt * 32 + f4 * 4);
            Xs[f4 * 4 + 0][row] = v.x;
            Xs[f4 * 4 + 1][row] = v.y;
            Xs[f4 * 4 + 2][row] = v.z;
            Xs[f4 * 4 + 3][row] = v.w;
        }
        #pragma unroll
        for (int l = 0; l < 2; ++l) {
            int lin = tid + l * 256;
            int k  = lin >> 4;
            int c4 = lin & 15;
            *(float4*)&Ws[k][c4 * 4] =
                *(const float4*)(Wsrc + (size_t)(kt * 32 + k) * CC + c4 * 4);
        }
        __syncthreads();

        #pragma unroll 8
        for (int k = 0; k < 32; ++k) {
            ulonglong2 xa = *(const ulonglong2*)&Xs[k][r0];
            ulonglong2 xb = *(const ulonglong2*)&Xs[k][r0 + 4];
            float4 w = *(const float4*)&Ws[k][c0];
            ull wx, wy, wz, ww;
            PACK2(wx, w.x, w.x);
            PACK2(wy, w.y, w.y);
            PACK2(wz, w.z, w.z);
            PACK2(ww, w.w, w.w);
            FMA2(acc[0][0], xa.x, wx, acc[0][0]);
            FMA2(acc[0][1], xa.x, wy, acc[0][1]);
            FMA2(acc[0][2], xa.x, wz, acc[0][2]);
            FMA2(acc[0][3], xa.x, ww, acc[0][3]);
            FMA2(acc[1][0], xa.y, wx, acc[1][0]);
            FMA2(acc[1][1], xa.y, wy, acc[1][1]);
            FMA2(acc[1][2], xa.y, wz, acc[1][2]);
            FMA2(acc[1][3], xa.y, ww, acc[1][3]);
            FMA2(acc[2][0], xb.x, wx, acc[2][0]);
            FMA2(acc[2][1], xb.x, wy, acc[2][1]);
            FMA2(acc[2][2], xb.x, wz, acc[2][2]);
            FMA2(acc[2][3], xb.x, ww, acc[2][3]);
            FMA2(acc[3][0], xb.y, wx, acc[3][0]);
            FMA2(acc[3][1], xb.y, wy, acc[3][1]);
            FMA2(acc[3][2], xb.y, wz, acc[3][2]);
            FMA2(acc[3][3], xb.y, ww, acc[3][3]);
        }
        __syncthreads();
    }

    float* dst = (isw2 ? g_feats2 : g_feats)
               + ((size_t)head * NN + n0 + r0) * CC + c0;
    const float4 as = *(const float4*)(a_self  + head * CC + c0);
    const float4 an = *(const float4*)(a_neigh + head * CC + c0);

    #pragma unroll
    for (int rp = 0; rp < 4; ++rp) {
        float lo0, hi0, lo1, hi1, lo2, hi2, lo3, hi3;
        UNPACK2(lo0, hi0, acc[rp][0]);
        UNPACK2(lo1, hi1, acc[rp][1]);
        UNPACK2(lo2, hi2, acc[rp][2]);
        UNPACK2(lo3, hi3, acc[rp][3]);
        *(float4*)(dst + (size_t)(2 * rp) * CC)     = make_float4(lo0, lo1, lo2, lo3);
        *(float4*)(dst + (size_t)(2 * rp + 1) * CC) = make_float4(hi0, hi1, hi2, hi3);

        if (!isw2) {
            float s0 = lo0 * as.x + lo1 * as.y + lo2 * as.z + lo3 * as.w;
            float t0 = lo0 * an.x + lo1 * an.y + lo2 * an.z + lo3 * an.w;
            float s1 = hi0 * as.x + hi1 * as.y + hi2 * as.z + hi3 * as.w;
            float t1 = hi0 * an.x + hi1 * an.y + hi2 * an.z + hi3 * an.w;
            #pragma unroll
            for (int o = 8; o; o >>= 1) {
                s0 += __shfl_xor_sync(0xffffffffu, s0, o);
                t0 += __shfl_xor_sync(0xffffffffu, t0, o);
                s1 += __shfl_xor_sync(0xffffffffu, s1, o);
                t1 += __shfl_xor_sync(0xffffffffu, t1, o);
            }
            if (tx == 0) {
                g_atts[head * NN + n0 + r0 + 2 * rp]     = s0;
                g_attn[head * NN + n0 + r0 + 2 * rp]     = t0;
                g_atts[head * NN + n0 + r0 + 2 * rp + 1] = s1;
                g_attn[head * NN + n0 + r0 + 2 * rp + 1] = t1;
            }
        }
    }
}

// ---------------------------------------------------------------------------
// k_attn: one 128-thread block per row. Mask precomputed by k_mask;
// one warp per head; fp32 float4-idx gather (exact path).
// ---------------------------------------------------------------------------
__global__ __launch_bounds__(128) void k_attn(
    const float* __restrict__ bias,
    float* __restrict__ out)
{
    __shared__ int   s_idx[MAXNB + 4];
    __shared__ float s_e[HH][MAXNB + 4];
    __shared__ int   s_wsum[4];
    __shared__ float s_out[HH][CC];

    const int i    = blockIdx.x;
    const int tid  = threadIdx.x;
    const int lane = tid & 31;
    const int warp = tid >> 5;

    // --- load precomputed presence word (coalesced 8B per thread) ---
    const ull mask = g_mask[(size_t)i * 128 + tid];
    const int lc = __popcll(mask);

    // --- warp shfl scan + cross-warp combine ---
    int v = lc;
    #pragma unroll
    for (int o = 1; o < 32; o <<= 1) {
        int u = __shfl_up_sync(0xffffffffu, v, o);
        if (lane >= o) v += u;
    }
    if (lane == 31) s_wsum[warp] = v;
    __syncthreads();
    int base = 0;
    #pragma unroll
    for (int w = 0; w < 4; ++w)
        if (w < warp) base += s_wsum[w];
    int cnt = s_wsum[0] + s_wsum[1] + s_wsum[2] + s_wsum[3];
    if (cnt > MAXNB) cnt = MAXNB;

    // --- compaction from the bitmask ---
    int p = base + v - lc;
    ull m2 = mask;
    while (m2) {
        int b = __ffsll((long long)m2) - 1;
        m2 &= m2 - 1;
        int col = 4 * tid + 512 * (b >> 2) + (b & 3);
        if (p < MAXNB) s_idx[p] = col;
        ++p;
    }
    if (tid < 3) s_idx[cnt + tid] = 0;       // pad for int4 gather reads
    __syncthreads();

    // --- per-head processing: warp h owns head h ---
    const int h = warp;
    const float si = g_atts[h * NN + i];
    const float* an = g_attn + (size_t)h * NN;

    float lmax = -1e30f;
    for (int j = lane; j < cnt; j += 32) {
        float l = si + an[s_idx[j]];
        l = (l > 0.f) ? l : 0.2f * l;        // LeakyReLU(0.2)
        s_e[h][j] = l;
        lmax = fmaxf(lmax, l);
    }
    #pragma unroll
    for (int o = 16; o; o >>= 1)
        lmax = fmaxf(lmax, __shfl_xor_sync(0xffffffffu, lmax, o));
    __syncwarp();

    float lsum = 0.f;
    for (int j = lane; j < cnt; j += 32) {
        float e = __expf(s_e[h][j] - lmax);
        s_e[h][j] = e;
        lsum += e;
    }
    if (lane < 3) s_e[h][cnt + lane] = 0.f;  // pad for float4 gather reads
    #pragma unroll
    for (int o = 16; o; o >>= 1)
        lsum += __shfl_xor_sync(0xffffffffu, lsum, o);
    float inv = 1.f / lsum;
    __syncwarp();

    // gather-aggregate: lane handles channels (lane, lane+32); 4 j per iter
    const float* fh = g_feats + (size_t)h * NN * CC;
    float acc0 = 0.f, acc1 = 0.f;
    for (int j = 0; j < cnt; j += 4) {
        float4 e4 = *(const float4*)&s_e[h][j];
        int4   i4 = *(const int4*)&s_idx[j];
        const float* f0 = fh + (size_t)i4.x * CC;
        const float* f1 = fh + (size_t)i4.y * CC;
        const float* f2 = fh + (size_t)i4.z * CC;
        const float* f3 = fh + (size_t)i4.w * CC;
        acc0 += e4.x * f0[lane];      acc1 += e4.x * f0[lane + 32];
        acc0 += e4.y * f1[lane];      acc1 += e4.y * f1[lane + 32];
        acc0 += e4.z * f2[lane];      acc1 += e4.z * f2[lane + 32];
        acc0 += e4.w * f3[lane];      acc1 += e4.w * f3[lane + 32];
    }
    s_out[h][lane]      = acc0 * inv;
    s_out[h][lane + 32] = acc1 * inv;
    __syncthreads();

    if (tid < CC) {
        float b = 0.f;
        #pragma unroll
        for (int hh = 0; hh < HH; ++hh)
            b += g_feats2[((size_t)hh * NN + i) * CC + tid] + bias[hh * CC + tid];
        float o = 0.25f * b
                + 0.25f * (s_out[0][tid] + s_out[1][tid] + s_out[2][tid] + s_out[3][tid]);
        out[(size_t)i * CC + tid] = (o > 0.f) ? o : 0.f;
    }
}

// ---------------------------------------------------------------------------
extern "C" void kernel_launch(void* const* d_in, const int* in_sizes, int n_in,
                              void* d_out, int out_size)
{
    const float* X       = (const float*)d_in[0];
    const float* A       = (const float*)d_in[1];
    const float* W1      = (const float*)d_in[2];
    const float* W2      = (const float*)d_in[3];
    const float* a_self  = (const float*)d_in[4];
    const float* a_neigh = (const float*)d_in[5];
    const float* bias    = (const float*)d_in[6];
    float* out = (float*)d_out;

    k_mask<<<NN / 2,      256>>>(A);
    k_proj<<<dim3(48, 8), 256>>>(X, W1, W2, a_self, a_neigh);
    k_attn<<<NN,          128>>>(bias, out);
}

// round 7
// speedup vs baseline: 1.2709x; 1.0189x over previous
#include <cuda_runtime.h>
#include <cuda_fp16.h>

#define NN 6144
#define FF 128
#define CC 64
#define HH 4
#define MAXNB 384

typedef unsigned long long ull;

#define PACK2(out, lo, hi) \
    asm("mov.b64 %0, {%1, %2};" : "=l"(out) : "f"(lo), "f"(hi))
#define UNPACK2(lo, hi, in) \
    asm("mov.b64 {%0, %1}, %2;" : "=f"(lo), "=f"(hi) : "l"(in))
#define FMA2(d, a, b, c) \
    asm("fma.rn.f32x2 %0, %1, %2, %3;" : "=l"(d) : "l"(a), "l"(b), "l"(c))

// Scratch (allocation-free: __device__ globals)
__device__ float  g_feats [HH * NN * CC];  // X@W1 per head (fp32)
__device__ __half g_featsh[HH * NN * CC];  // fp16 copy (gather operand)
__device__ float  g_feats2[HH * NN * CC];  // X@W2 per head (fp32)
__device__ float  g_atts  [HH * NN];       // self logit term
__device__ float  g_attn  [HH * NN];       // neighbor logit term
__device__ ull    g_mask  [NN * 128];      // 48-bit presence words per row

// ---------------------------------------------------------------------------
// k_pre: heterogeneous kernel. 3456 CTAs x 256 threads.
//   pid % 9 == 0  -> proj CTA (384 total): tiled SGEMM (FFMA2) + att epilogue
//   otherwise     -> mask CTA (3072 total): pure-streaming adjacency scan
// Interleaving co-schedules DRAM-bound mask CTAs with FFMA-bound proj CTAs.
// ---------------------------------------------------------------------------
__global__ __launch_bounds__(256) void k_pre(
    const float* __restrict__ A,
    const float* __restrict__ X,
    const float* __restrict__ W1,
    const float* __restrict__ W2,
    const float* __restrict__ a_self,
    const float* __restrict__ a_neigh)
{
    const int pid = blockIdx.x;
    const int tid = threadIdx.x;

    if (pid % 9 != 0) {
        // ------------------- mask CTA: 2 rows, streaming scan -------------------
        const int m = pid - pid / 9 - 1;           // 0..3071
        const int t = tid & 127;                   // word within row
        const int i = m * 2 + (tid >> 7);
        const float* Ai = A + (size_t)i * NN;

        ull mask = 0ull;
        #pragma unroll
        for (int k = 0; k < 12; ++k) {
            float4 v = *(const float4*)(Ai + 4 * t + 512 * k);
            unsigned mm = (unsigned)(v.x != 0.f)
                        | ((unsigned)(v.y != 0.f) << 1)
                        | ((unsigned)(v.z != 0.f) << 2)
                        | ((unsigned)(v.w != 0.f) << 3);
            mask |= (ull)mm << (4 * k);
        }
        g_mask[(size_t)i * 128 + t] = mask;
        return;
    }

    // ---------------------- proj CTA: tiled SGEMM ----------------------
    __shared__ float Xs[32][132];   // [k][m], stride 132 (16B-aligned rows)
    __shared__ float Ws[32][64];    // [k][n]

    const int p    = pid / 9;       // 0..383
    const int n0   = (p % 48) * 128;
    const int yy   = p / 48;        // 0..7
    const int head = yy >> 1;
    const int isw2 = yy & 1;
    const float* Wsrc = (isw2 ? W2 : W1) + (size_t)head * FF * CC;

    const int tx = tid & 15;
    const int ty = tid >> 4;
    const int c0 = tx * 4;
    const int r0 = ty * 8;

    ull acc[4][4];
    #pragma unroll
    for (int rp = 0; rp < 4; ++rp)
        acc[rp][0] = acc[rp][1] = acc[rp][2] = acc[rp][3] = 0ull;

    for (int kt = 0; kt < 4; ++kt) {
        #pragma unroll
        for (int l = 0; l < 4; ++l) {
            int lin = tid + l * 256;
            int row = lin >> 3;
            int f4  = lin & 7;
            float4 v = *(const float4*)(X + (size_t)(n0 + row) * FF + kt * 32 + f4 * 4);
            Xs[f4 * 4 + 0][row] = v.x;
            Xs[f4 * 4 + 1][row] = v.y;
            Xs[f4 * 4 + 2][row] = v.z;
            Xs[f4 * 4 + 3][row] = v.w;
        }
        #pragma unroll
        for (int l = 0; l < 2; ++l) {
            int lin = tid + l * 256;
            int k  = lin >> 4;
            int c4 = lin & 15;
            *(float4*)&Ws[k][c4 * 4] =
                *(const float4*)(Wsrc + (size_t)(kt * 32 + k) * CC + c4 * 4);
        }
        __syncthreads();

        #pragma unroll 8
        for (int k = 0; k < 32; ++k) {
            ulonglong2 xa = *(const ulonglong2*)&Xs[k][r0];
            ulonglong2 xb = *(const ulonglong2*)&Xs[k][r0 + 4];
            float4 w = *(const float4*)&Ws[k][c0];
            ull wx, wy, wz, ww;
            PACK2(wx, w.x, w.x);
            PACK2(wy, w.y, w.y);
            PACK2(wz, w.z, w.z);
            PACK2(ww, w.w, w.w);
            FMA2(acc[0][0], xa.x, wx, acc[0][0]);
            FMA2(acc[0][1], xa.x, wy, acc[0][1]);
            FMA2(acc[0][2], xa.x, wz, acc[0][2]);
            FMA2(acc[0][3], xa.x, ww, acc[0][3]);
            FMA2(acc[1][0], xa.y, wx, acc[1][0]);
            FMA2(acc[1][1], xa.y, wy, acc[1][1]);
            FMA2(acc[1][2], xa.y, wz, acc[1][2]);
            FMA2(acc[1][3], xa.y, ww, acc[1][3]);
            FMA2(acc[2][0], xb.x, wx, acc[2][0]);
            FMA2(acc[2][1], xb.x, wy, acc[2][1]);
            FMA2(acc[2][2], xb.x, wz, acc[2][2]);
            FMA2(acc[2][3], xb.x, ww, acc[2][3]);
            FMA2(acc[3][0], xb.y, wx, acc[3][0]);
            FMA2(acc[3][1], xb.y, wy, acc[3][1]);
            FMA2(acc[3][2], xb.y, wz, acc[3][2]);
            FMA2(acc[3][3], xb.y, ww, acc[3][3]);
        }
        __syncthreads();
    }

    float* dst = (isw2 ? g_feats2 : g_feats)
               + ((size_t)head * NN + n0 + r0) * CC + c0;
    const float4 as = *(const float4*)(a_self  + head * CC + c0);
    const float4 an = *(const float4*)(a_neigh + head * CC + c0);

    #pragma unroll
    for (int rp = 0; rp < 4; ++rp) {
        float lo0, hi0, lo1, hi1, lo2, hi2, lo3, hi3;
        UNPACK2(lo0, hi0, acc[rp][0]);
        UNPACK2(lo1, hi1, acc[rp][1]);
        UNPACK2(lo2, hi2, acc[rp][2]);
        UNPACK2(lo3, hi3, acc[rp][3]);
        *(float4*)(dst + (size_t)(2 * rp) * CC)     = make_float4(lo0, lo1, lo2, lo3);
        *(float4*)(dst + (size_t)(2 * rp + 1) * CC) = make_float4(hi0, hi1, hi2, hi3);

        if (!isw2) {
            float s0 = lo0 * as.x + lo1 * as.y + lo2 * as.z + lo3 * as.w;
            float t0 = lo0 * an.x + lo1 * an.y + lo2 * an.z + lo3 * an.w;
            float s1 = hi0 * as.x + hi1 * as.y + hi2 * as.z + hi3 * as.w;
            float t1 = hi0 * an.x + hi1 * an.y + hi2 * an.z + hi3 * an.w;
            #pragma unroll
            for (int o = 8; o; o >>= 1) {
                s0 += __shfl_xor_sync(0xffffffffu, s0, o);
                t0 += __shfl_xor_sync(0xffffffffu, t0, o);
                s1 += __shfl_xor_sync(0xffffffffu, s1, o);
                t1 += __shfl_xor_sync(0xffffffffu, t1, o);
            }
            if (tx == 0) {
                g_atts[head * NN + n0 + r0 + 2 * rp]     = s0;
                g_attn[head * NN + n0 + r0 + 2 * rp]     = t0;
                g_atts[head * NN + n0 + r0 + 2 * rp + 1] = s1;
                g_attn[head * NN + n0 + r0 + 2 * rp + 1] = t1;
            }
        }
    }
}

// ---------------------------------------------------------------------------
// k_half: streaming convert g_feats (fp32) -> g_featsh (fp16).
// 1536 CTAs x 256 thr, 4 floats per thread.
// ---------------------------------------------------------------------------
__global__ __launch_bounds__(256) void k_half()
{
    const size_t idx = ((size_t)blockIdx.x * 256 + threadIdx.x) * 4;
    float4 v = *(const float4*)(g_feats + idx);
    __half2 a = __floats2half2_rn(v.x, v.y);
    __half2 b = __floats2half2_rn(v.z, v.w);
    uint2 pk;
    pk.x = *(unsigned*)&a;
    pk.y = *(unsigned*)&b;
    *(uint2*)(g_featsh + idx) = pk;
}

// ---------------------------------------------------------------------------
// k_attn: one 128-thread block per row; precomputed mask; one warp per head;
// half2 gather (one LDG.32 per neighbor per lane = full 128B row per warp).
// ---------------------------------------------------------------------------
__global__ __launch_bounds__(128) void k_attn(
    const float* __restrict__ bias,
    float* __restrict__ out)
{
    __shared__ int   s_idx[MAXNB + 4];
    __shared__ float s_e[HH][MAXNB + 4];
    __shared__ int   s_wsum[4];
    __shared__ float s_out[HH][CC];

    const int i    = blockIdx.x;
    const int tid  = threadIdx.x;
    const int lane = tid & 31;
    const int warp = tid >> 5;

    // --- load precomputed presence word (coalesced 8B per thread) ---
    const ull mask = g_mask[(size_t)i * 128 + tid];
    const int lc = __popcll(mask);

    // --- warp shfl scan + cross-warp combine ---
    int v = lc;
    #pragma unroll
    for (int o = 1; o < 32; o <<= 1) {
        int u = __shfl_up_sync(0xffffffffu, v, o);
        if (lane >= o) v += u;
    }
    if (lane == 31) s_wsum[warp] = v;
    __syncthreads();
    int base = 0;
    #pragma unroll
    for (int w = 0; w < 4; ++w)
        if (w < warp) base += s_wsum[w];
    int cnt = s_wsum[0] + s_wsum[1] + s_wsum[2] + s_wsum[3];
    if (cnt > MAXNB) cnt = MAXNB;

    // --- compaction from the bitmask ---
    int p = base + v - lc;
    ull m2 = mask;
    while (m2) {
        int b = __ffsll((long long)m2) - 1;
        m2 &= m2 - 1;
        int col = 4 * tid + 512 * (b >> 2) + (b & 3);
        if (p < MAXNB) s_idx[p] = col;
        ++p;
    }
    if (tid < 3) s_idx[cnt + tid] = 0;       // pad for int4 gather reads
    __syncthreads();

    // --- per-head processing: warp h owns head h ---
    const int h = warp;
    const float si = g_atts[h * NN + i];
    const float* an = g_attn + (size_t)h * NN;

    float lmax = -1e30f;
    for (int j = lane; j < cnt; j += 32) {
        float l = si + an[s_idx[j]];
        l = (l > 0.f) ? l : 0.2f * l;        // LeakyReLU(0.2)
        s_e[h][j] = l;
        lmax = fmaxf(lmax, l);
    }
    #pragma unroll
    for (int o = 16; o; o >>= 1)
        lmax = fmaxf(lmax, __shfl_xor_sync(0xffffffffu, lmax, o));
    __syncwarp();

    float lsum = 0.f;
    for (int j = lane; j < cnt; j += 32) {
        float e = __expf(s_e[h][j] - lmax);
        s_e[h][j] = e;
        lsum += e;
    }
    if (lane < 3) s_e[h][cnt + lane] = 0.f;  // pad for float4 gather reads
    #pragma unroll
    for (int o = 16; o; o >>= 1)
        lsum += __shfl_xor_sync(0xffffffffu, lsum, o);
    float inv = 1.f / lsum;
    __syncwarp();

    // gather-aggregate: lane owns channels (2*lane, 2*lane+1); one half2
    // load per neighbor per lane; 4 neighbors per iteration.
    const __half2* fh = (const __half2*)g_featsh + (size_t)h * NN * (CC / 2);
    float acc0 = 0.f, acc1 = 0.f;
    for (int j = 0; j < cnt; j += 4) {
        float4 e4 = *(const float4*)&s_e[h][j];
        int4   i4 = *(const int4*)&s_idx[j];
        float2 f0 = __half22float2(fh[(size_t)i4.x * (CC / 2) + lane]);
        float2 f1 = __half22float2(fh[(size_t)i4.y * (CC / 2) + lane]);
        float2 f2 = __half22float2(fh[(size_t)i4.z * (CC / 2) + lane]);
        float2 f3 = __half22float2(fh[(size_t)i4.w * (CC / 2) + lane]);
        acc0 += e4.x * f0.x;   acc1 += e4.x * f0.y;
        acc0 += e4.y * f1.x;   acc1 += e4.y * f1.y;
        acc0 += e4.z * f2.x;   acc1 += e4.z * f2.y;
        acc0 += e4.w * f3.x;   acc1 += e4.w * f3.y;
    }
    s_out[h][2 * lane]     = acc0 * inv;
    s_out[h][2 * lane + 1] = acc1 * inv;
    __syncthreads();

    if (tid < CC) {
        float b = 0.f;
        #pragma unroll
        for (int hh = 0; hh < HH; ++hh)
            b += g_feats2[((size_t)hh * NN + i) * CC + tid] + bias[hh * CC + tid];
        float o = 0.25f * b
                + 0.25f * (s_out[0][tid] + s_out[1][tid] + s_out[2][tid] + s_out[3][tid]);
        out[(size_t)i * CC + tid] = (o > 0.f) ? o : 0.f;
    }
}

// ---------------------------------------------------------------------------
extern "C" void kernel_launch(void* const* d_in, const int* in_sizes, int n_in,
                              void* d_out, int out_size)
{
    const float* X       = (const float*)d_in[0];
    const float* A       = (const float*)d_in[1];
    const float* W1      = (const float*)d_in[2];
    const float* W2      = (const float*)d_in[3];
    const float* a_self  = (const float*)d_in[4];
    const float* a_neigh = (const float*)d_in[5];
    const float* bias    = (const float*)d_in[6];
    float* out = (float*)d_out;

    k_pre <<<3456, 256>>>(A, X, W1, W2, a_self, a_neigh);
    k_half<<<1536, 256>>>();
    k_attn<<<NN,   128>>>(bias, out);
}

// round 8
// speedup vs baseline: 1.4492x; 1.1403x over previous
#include <cuda_runtime.h>

#define NN 6144
#define FF 128
#define CC 64
#define HH 4
#define MAXNB 384

typedef unsigned long long ull;

#define PACK2(out, lo, hi) \
    asm("mov.b64 %0, {%1, %2};" : "=l"(out) : "f"(lo), "f"(hi))
#define UNPACK2(lo, hi, in) \
    asm("mov.b64 {%0, %1}, %2;" : "=f"(lo), "=f"(hi) : "l"(in))
#define FMA2(d, a, b, c) \
    asm("fma.rn.f32x2 %0, %1, %2, %3;" : "=l"(d) : "l"(a), "l"(b), "l"(c))

// Scratch (allocation-free: __device__ globals)
__device__ float  g_feats [HH * NN * CC];  // X@W1 per head (fp32)
__device__ float  g_feats2[HH * NN * CC];  // X@W2 per head (fp32)
__device__ float4 g_atts4 [NN];            // self logit terms, interleaved [n][h]
__device__ float4 g_attn4 [NN];            // neighbor logit terms, interleaved [n][h]

// ---------------------------------------------------------------------------
// k_proj: tiled SGEMM with f32x2 packed FFMA + att-vector epilogue.
// grid (48, 8): y = head*2 + {0:W1, 1:W2}. BM=128, BN=64(=C), BK=32,
// 256 threads. Thread tile 8 rows x 4 cols, rows packed in pairs (FFMA2).
// ---------------------------------------------------------------------------
__global__ __launch_bounds__(256) void k_proj(
    const float* __restrict__ X,
    const float* __restrict__ W1,
    const float* __restrict__ W2,
    const float* __restrict__ a_self,
    const float* __restrict__ a_neigh)
{
    __shared__ float Xs[32][132];   // [k][m], stride 132 (16B-aligned rows)
    __shared__ float Ws[32][64];    // [k][n]

    const int tid  = threadIdx.x;
    const int n0   = blockIdx.x * 128;
    const int head = blockIdx.y >> 1;
    const int isw2 = blockIdx.y & 1;
    const float* Wsrc = (isw2 ? W2 : W1) + (size_t)head * FF * CC;

    const int tx = tid & 15;        // col group: c0 = tx*4
    const int ty = tid >> 4;        // row group: r0 = ty*8
    const int c0 = tx * 4;
    const int r0 = ty * 8;

    ull acc[4][4];                  // [rowpair][col]
    #pragma unroll
    for (int rp = 0; rp < 4; ++rp)
        acc[rp][0] = acc[rp][1] = acc[rp][2] = acc[rp][3] = 0ull;

    for (int kt = 0; kt < 4; ++kt) {
        #pragma unroll
        for (int l = 0; l < 4; ++l) {
            int lin = tid + l * 256;
            int row = lin >> 3;
            int f4  = lin & 7;
            float4 v = *(const float4*)(X + (size_t)(n0 + row) * FF + kt * 32 + f4 * 4);
            Xs[f4 * 4 + 0][row] = v.x;
            Xs[f4 * 4 + 1][row] = v.y;
            Xs[f4 * 4 + 2][row] = v.z;
            Xs[f4 * 4 + 3][row] = v.w;
        }
        #pragma unroll
        for (int l = 0; l < 2; ++l) {
            int lin = tid + l * 256;
            int k  = lin >> 4;
            int c4 = lin & 15;
            *(float4*)&Ws[k][c4 * 4] =
                *(const float4*)(Wsrc + (size_t)(kt * 32 + k) * CC + c4 * 4);
        }
        __syncthreads();

        #pragma unroll 8
        for (int k = 0; k < 32; ++k) {
            ulonglong2 xa = *(const ulonglong2*)&Xs[k][r0];
            ulonglong2 xb = *(const ulonglong2*)&Xs[k][r0 + 4];
            float4 w = *(const float4*)&Ws[k][c0];
            ull wx, wy, wz, ww;
            PACK2(wx, w.x, w.x);
            PACK2(wy, w.y, w.y);
            PACK2(wz, w.z, w.z);
            PACK2(ww, w.w, w.w);
            FMA2(acc[0][0], xa.x, wx, acc[0][0]);
            FMA2(acc[0][1], xa.x, wy, acc[0][1]);
            FMA2(acc[0][2], xa.x, wz, acc[0][2]);
            FMA2(acc[0][3], xa.x, ww, acc[0][3]);
            FMA2(acc[1][0], xa.y, wx, acc[1][0]);
            FMA2(acc[1][1], xa.y, wy, acc[1][1]);
            FMA2(acc[1][2], xa.y, wz, acc[1][2]);
            FMA2(acc[1][3], xa.y, ww, acc[1][3]);
            FMA2(acc[2][0], xb.x, wx, acc[2][0]);
            FMA2(acc[2][1], xb.x, wy, acc[2][1]);
            FMA2(acc[2][2], xb.x, wz, acc[2][2]);
            FMA2(acc[2][3], xb.x, ww, acc[2][3]);
            FMA2(acc[3][0], xb.y, wx, acc[3][0]);
            FMA2(acc[3][1], xb.y, wy, acc[3][1]);
            FMA2(acc[3][2], xb.y, wz, acc[3][2]);
            FMA2(acc[3][3], xb.y, ww, acc[3][3]);
        }
        __syncthreads();
    }

    float* dst = (isw2 ? g_feats2 : g_feats)
               + ((size_t)head * NN + n0 + r0) * CC + c0;
    const float4 as = *(const float4*)(a_self  + head * CC + c0);
    const float4 an = *(const float4*)(a_neigh + head * CC + c0);

    #pragma unroll
    for (int rp = 0; rp < 4; ++rp) {
        float lo0, hi0, lo1, hi1, lo2, hi2, lo3, hi3;
        UNPACK2(lo0, hi0, acc[rp][0]);
        UNPACK2(lo1, hi1, acc[rp][1]);
        UNPACK2(lo2, hi2, acc[rp][2]);
        UNPACK2(lo3, hi3, acc[rp][3]);
        *(float4*)(dst + (size_t)(2 * rp) * CC)     = make_float4(lo0, lo1, lo2, lo3);
        *(float4*)(dst + (size_t)(2 * rp + 1) * CC) = make_float4(hi0, hi1, hi2, hi3);

        if (!isw2) {
            float s0 = lo0 * as.x + lo1 * as.y + lo2 * as.z + lo3 * as.w;
            float t0 = lo0 * an.x + lo1 * an.y + lo2 * an.z + lo3 * an.w;
            float s1 = hi0 * as.x + hi1 * as.y + hi2 * as.z + hi3 * as.w;
            float t1 = hi0 * an.x + hi1 * an.y + hi2 * an.z + hi3 * an.w;
            #pragma unroll
            for (int o = 8; o; o >>= 1) {
                s0 += __shfl_xor_sync(0xffffffffu, s0, o);
                t0 += __shfl_xor_sync(0xffffffffu, t0, o);
                s1 += __shfl_xor_sync(0xffffffffu, s1, o);
                t1 += __shfl_xor_sync(0xffffffffu, t1, o);
            }
            if (tx == 0) {
                // interleaved [n][h] layout for single-float4 logit gathers
                ((float*)g_atts4)[(n0 + r0 + 2 * rp) * 4 + head]     = s0;
                ((float*)g_attn4)[(n0 + r0 + 2 * rp) * 4 + head]     = t0;
                ((float*)g_atts4)[(n0 + r0 + 2 * rp + 1) * 4 + head] = s1;
                ((float*)g_attn4)[(n0 + r0 + 2 * rp + 1) * 4 + head] = t1;
            }
        }
    }
}

// ---------------------------------------------------------------------------
// k_attn: fused A-scan + sparse softmax-aggregate. One 128-thread block per
// row. Bitmask compaction (A read once, coalesced); logits for ALL 4 heads
// via one float4 gather per neighbor; byte-offset float2 gather per head.
// ---------------------------------------------------------------------------
__global__ __launch_bounds__(128) void k_attn(
    const float* __restrict__ A,
    const float* __restrict__ bias,
    float* __restrict__ out)
{
    __shared__ int   s_idx[MAXNB + 4];       // byte offsets (col * 256)
    __shared__ float s_e[HH][MAXNB + 4];
    __shared__ int   s_wsum[4];
    __shared__ float s_redm[4][4];           // [warp][head] max partials
    __shared__ float s_reds[4][4];           // [warp][head] sum partials
    __shared__ float s_out[HH][CC];

    const int i    = blockIdx.x;
    const int tid  = threadIdx.x;
    const int lane = tid & 31;
    const int warp = tid >> 5;
    const float* Ai = A + (size_t)i * NN;

    // --- coalesced scan, presence bitmask in a register ---
    ull mask = 0ull;
    #pragma unroll
    for (int k = 0; k < 12; ++k) {
        float4 v = *(const float4*)(Ai + 4 * tid + 512 * k);
        unsigned m = (unsigned)(v.x != 0.f)
                   | ((unsigned)(v.y != 0.f) << 1)
                   | ((unsigned)(v.z != 0.f) << 2)
                   | ((unsigned)(v.w != 0.f) << 3);
        mask |= (ull)m << (4 * k);
    }
    const int lc = __popcll(mask);

    // --- warp shfl scan + cross-warp combine ---
    int v = lc;
    #pragma unroll
    for (int o = 1; o < 32; o <<= 1) {
        int u = __shfl_up_sync(0xffffffffu, v, o);
        if (lane >= o) v += u;
    }
    if (lane == 31) s_wsum[warp] = v;
    __syncthreads();
    int base = 0;
    #pragma unroll
    for (int w = 0; w < 4; ++w)
        if (w < warp) base += s_wsum[w];
    int cnt = s_wsum[0] + s_wsum[1] + s_wsum[2] + s_wsum[3];
    if (cnt > MAXNB) cnt = MAXNB;

    // --- compaction: store BYTE offsets (col << 8 = col * CC * 4) ---
    int p = base + v - lc;
    ull m2 = mask;
    while (m2) {
        int b = __ffsll((long long)m2) - 1;
        m2 &= m2 - 1;
        int col = 4 * tid + 512 * (b >> 2) + (b & 3);
        if (p < MAXNB) s_idx[p] = col << 8;
        ++p;
    }
    if (tid < 3)  s_idx[cnt + tid] = 0;                      // pad (int4 reads)
    if (tid < 12) s_e[tid & 3][cnt + (tid >> 2)] = 0.f;      // pad (float4 reads)
    __syncthreads();

    // --- logit pass: ONE float4 gather per neighbor serves all 4 heads ---
    const float4 si4 = g_atts4[i];
    float m0 = -1e30f, m1 = -1e30f, m2f = -1e30f, m3 = -1e30f;
    for (int j = tid; j < cnt; j += 128) {
        int off = s_idx[j];
        float4 an = *(const float4*)((const char*)g_attn4 + (off >> 4));
        float l0 = si4.x + an.x;  l0 = (l0 > 0.f) ? l0 : 0.2f * l0;
        float l1 = si4.y + an.y;  l1 = (l1 > 0.f) ? l1 : 0.2f * l1;
        float l2 = si4.z + an.z;  l2 = (l2 > 0.f) ? l2 : 0.2f * l2;
        float l3 = si4.w + an.w;  l3 = (l3 > 0.f) ? l3 : 0.2f * l3;
        s_e[0][j] = l0;  s_e[1][j] = l1;  s_e[2][j] = l2;  s_e[3][j] = l3;
        m0 = fmaxf(m0, l0);  m1 = fmaxf(m1, l1);
        m2f = fmaxf(m2f, l2);  m3 = fmaxf(m3, l3);
    }
    #pragma unroll
    for (int o = 16; o; o >>= 1) {
        m0  = fmaxf(m0,  __shfl_xor_sync(0xffffffffu, m0,  o));
        m1  = fmaxf(m1,  __shfl_xor_sync(0xffffffffu, m1,  o));
        m2f = fmaxf(m2f, __shfl_xor_sync(0xffffffffu, m2f, o));
        m3  = fmaxf(m3,  __shfl_xor_sync(0xffffffffu, m3,  o));
    }
    if (lane == 0)
        *(float4*)&s_redm[warp][0] = make_float4(m0, m1, m2f, m3);
    __syncthreads();
    {
        float4 a = *(float4*)&s_redm[0][0];
        float4 b = *(float4*)&s_redm[1][0];
        float4 c = *(float4*)&s_redm[2][0];
        float4 d = *(float4*)&s_redm[3][0];
        m0  = fmaxf(fmaxf(a.x, b.x), fmaxf(c.x, d.x));
        m1  = fmaxf(fmaxf(a.y, b.y), fmaxf(c.y, d.y));
        m2f = fmaxf(fmaxf(a.z, b.z), fmaxf(c.z, d.z));
        m3  = fmaxf(fmaxf(a.w, b.w), fmaxf(c.w, d.w));
    }

    // --- exp pass (smem only) ---
    float q0 = 0.f, q1 = 0.f, q2 = 0.f, q3 = 0.f;
    for (int j = tid; j < cnt; j += 128) {
        float e0 = __expf(s_e[0][j] - m0);   s_e[0][j] = e0;  q0 += e0;
        float e1 = __expf(s_e[1][j] - m1);   s_e[1][j] = e1;  q1 += e1;
        float e2 = __expf(s_e[2][j] - m2f);  s_e[2][j] = e2;  q2 += e2;
        float e3 = __expf(s_e[3][j] - m3);   s_e[3][j] = e3;  q3 += e3;
    }
    #pragma unroll
    for (int o = 16; o; o >>= 1) {
        q0 += __shfl_xor_sync(0xffffffffu, q0, o);
        q1 += __shfl_xor_sync(0xffffffffu, q1, o);
        q2 += __shfl_xor_sync(0xffffffffu, q2, o);
        q3 += __shfl_xor_sync(0xffffffffu, q3, o);
    }
    if (lane == 0)
        *(float4*)&s_reds[warp][0] = make_float4(q0, q1, q2, q3);
    __syncthreads();

    // --- gather-aggregate: warp h owns head h; float2 per neighbor per lane ---
    const int h = warp;
    const float inv = 1.f / (s_reds[0][h] + s_reds[1][h] + s_reds[2][h] + s_reds[3][h]);
    const char* fh = (const char*)(g_feats + (size_t)h * NN * CC) + lane * 8;
    float acc0 = 0.f, acc1 = 0.f;
    for (int j = 0; j < cnt; j += 4) {
        float4 e4 = *(const float4*)&s_e[h][j];
        int4   o4 = *(const int4*)&s_idx[j];
        float2 f0 = *(const float2*)(fh + o4.x);
        float2 f1 = *(const float2*)(fh + o4.y);
        float2 f2 = *(const float2*)(fh + o4.z);
        float2 f3 = *(const float2*)(fh + o4.w);
        acc0 += e4.x * f0.x;   acc1 += e4.x * f0.y;
        acc0 += e4.y * f1.x;   acc1 += e4.y * f1.y;
        acc0 += e4.z * f2.x;   acc1 += e4.z * f2.y;
        acc0 += e4.w * f3.x;   acc1 += e4.w * f3.y;
    }
    s_out[h][2 * lane]     = acc0 * inv;
    s_out[h][2 * lane + 1] = acc1 * inv;
    __syncthreads();

    if (tid < CC) {
        float b = 0.f;
        #pragma unroll
        for (int hh = 0; hh < HH; ++hh)
            b += g_feats2[((size_t)hh * NN + i) * CC + tid] + bias[hh * CC + tid];
        float o = 0.25f * b
                + 0.25f * (s_out[0][tid] + s_out[1][tid] + s_out[2][tid] + s_out[3][tid]);
        out[(size_t)i * CC + tid] = (o > 0.f) ? o : 0.f;
    }
}

// ---------------------------------------------------------------------------
extern "C" void kernel_launch(void* const* d_in, const int* in_sizes, int n_in,
                              void* d_out, int out_size)
{
    const float* X       = (const float*)d_in[0];
    const float* A       = (const float*)d_in[1];
    const float* W1      = (const float*)d_in[2];
    const float* W2      = (const float*)d_in[3];
    const float* a_self  = (const float*)d_in[4];
    const float* a_neigh = (const float*)d_in[5];
    const float* bias    = (const float*)d_in[6];
    float* out = (float*)d_out;

    k_proj<<<dim3(48, 8), 256>>>(X, W1, W2, a_self, a_neigh);
    k_attn<<<NN,          128>>>(A, bias, out);
}